// round 1
// baseline (speedup 1.0000x reference)
#include <cuda_runtime.h>
#include <cstddef>

#define NPTS 4096
#define DD   256
#define TSTEPS 8

__device__ float g_K[(size_t)NPTS * NPTS];     // 64 MB scratch: kernel matrix
__device__ float g_Z[2][(size_t)NPTS * DD];    // ping-pong state
__device__ float g_sq[NPTS];                   // row squared norms

__constant__ float c_inv2rho2 = 1.0f / 512.0f; // 1/(2*16*16)
__constant__ float c_dt       = 0.125f;        // 1/T

// ---------------------------------------------------------------------------
// Row squared norms: one warp per row.
// ---------------------------------------------------------------------------
__global__ void k_sq(const float* __restrict__ Z, float* __restrict__ sq) {
    int warp = (blockIdx.x * blockDim.x + threadIdx.x) >> 5;
    int lane = threadIdx.x & 31;
    if (warp >= NPTS) return;
    const float* row = Z + (size_t)warp * DD;
    float s = 0.0f;
#pragma unroll
    for (int k = lane; k < DD; k += 32) {
        float v = row[k];
        s += v * v;
    }
#pragma unroll
    for (int o = 16; o > 0; o >>= 1) s += __shfl_xor_sync(0xffffffffu, s, o);
    if (lane == 0) sq[warp] = s;
}

// ---------------------------------------------------------------------------
// K[i,j] = exp(-(sq_i + sq_j - 2*Z_i.Z_j)/(2 rho^2))
// 64x64 output tile per block, 256 threads, 4x4 micro-tile per thread.
// ---------------------------------------------------------------------------
__global__ void k_gram_exp(const float* __restrict__ Z,
                           const float* __restrict__ sq,
                           float* __restrict__ Kout) {
    __shared__ float As[16][64];
    __shared__ float Bs[16][64];

    const int i0 = blockIdx.y * 64;
    const int j0 = blockIdx.x * 64;
    const int tid = threadIdx.x;
    const int tx = tid & 15;
    const int ty = tid >> 4;

    float acc[4][4] = {};

    for (int k0 = 0; k0 < DD; k0 += 16) {
        // Load 64x16 tiles of Z rows (both i-side and j-side), transposed in smem.
        {
            int ii = tid >> 2;
            int kk = (tid & 3) * 4;
            float4 v = *(const float4*)(Z + (size_t)(i0 + ii) * DD + k0 + kk);
            As[kk + 0][ii] = v.x; As[kk + 1][ii] = v.y;
            As[kk + 2][ii] = v.z; As[kk + 3][ii] = v.w;
            float4 w = *(const float4*)(Z + (size_t)(j0 + ii) * DD + k0 + kk);
            Bs[kk + 0][ii] = w.x; Bs[kk + 1][ii] = w.y;
            Bs[kk + 2][ii] = w.z; Bs[kk + 3][ii] = w.w;
        }
        __syncthreads();
#pragma unroll
        for (int kk = 0; kk < 16; kk++) {
            float4 a = *(const float4*)&As[kk][ty * 4];
            float4 b = *(const float4*)&Bs[kk][tx * 4];
            float av[4] = {a.x, a.y, a.z, a.w};
            float bv[4] = {b.x, b.y, b.z, b.w};
#pragma unroll
            for (int r = 0; r < 4; r++)
#pragma unroll
                for (int c = 0; c < 4; c++) acc[r][c] += av[r] * bv[c];
        }
        __syncthreads();
    }

#pragma unroll
    for (int r = 0; r < 4; r++) {
        int i = i0 + ty * 4 + r;
        float si = sq[i];
        float4 sj = *(const float4*)(sq + j0 + tx * 4);
        float sjv[4] = {sj.x, sj.y, sj.z, sj.w};
        float4 o;
        float ov[4];
#pragma unroll
        for (int c = 0; c < 4; c++) {
            float dist = si + sjv[c] - 2.0f * acc[r][c];
            ov[c] = expf(-dist * c_inv2rho2);
        }
        o.x = ov[0]; o.y = ov[1]; o.z = ov[2]; o.w = ov[3];
        *(float4*)(Kout + (size_t)i * NPTS + j0 + tx * 4) = o;
    }
}

// ---------------------------------------------------------------------------
// Znew = Z + dt * ( K @ A_t  +  Z @ Aaff_t^T  +  b_t )
// Output tile 64 rows x 64 cols (D=256 -> gridDim.x = 4), 4x4 micro-tile.
// ---------------------------------------------------------------------------
__global__ void k_step(const float* __restrict__ Z,
                       const float* __restrict__ Kmat,
                       const float* __restrict__ At,    // [NPTS, DD]
                       const float* __restrict__ Aaff,  // [DD, DD]
                       const float* __restrict__ baff,  // [DD]
                       float* __restrict__ Znew) {
    __shared__ float As[16][64];
    __shared__ float Bs[16][64];

    const int i0 = blockIdx.y * 64;
    const int j0 = blockIdx.x * 64;
    const int tid = threadIdx.x;
    const int tx = tid & 15;
    const int ty = tid >> 4;

    float acc[4][4] = {};

    // --- K @ A_t : reduce over NPTS ---
    for (int k0 = 0; k0 < NPTS; k0 += 16) {
        {
            // A-side: K rows i0..i0+63, cols k0..k0+15 (transposed store)
            int ii = tid >> 2;
            int kk = (tid & 3) * 4;
            float4 v = *(const float4*)(Kmat + (size_t)(i0 + ii) * NPTS + k0 + kk);
            As[kk + 0][ii] = v.x; As[kk + 1][ii] = v.y;
            As[kk + 2][ii] = v.z; As[kk + 3][ii] = v.w;
            // B-side: A_t rows k0..k0+15, cols j0..j0+63 (direct store)
            int kk2 = tid >> 4;
            int jj  = (tid & 15) * 4;
            float4 w = *(const float4*)(At + (size_t)(k0 + kk2) * DD + j0 + jj);
            *(float4*)&Bs[kk2][jj] = w;
        }
        __syncthreads();
#pragma unroll
        for (int kk = 0; kk < 16; kk++) {
            float4 a = *(const float4*)&As[kk][ty * 4];
            float4 b = *(const float4*)&Bs[kk][tx * 4];
            float av[4] = {a.x, a.y, a.z, a.w};
            float bv[4] = {b.x, b.y, b.z, b.w};
#pragma unroll
            for (int r = 0; r < 4; r++)
#pragma unroll
                for (int c = 0; c < 4; c++) acc[r][c] += av[r] * bv[c];
        }
        __syncthreads();
    }

    // --- Z @ Aaff^T : acc[i][j] += sum_e Z[i,e] * Aaff[j,e], reduce over DD ---
    for (int e0 = 0; e0 < DD; e0 += 16) {
        {
            int ii = tid >> 2;
            int kk = (tid & 3) * 4;
            float4 v = *(const float4*)(Z + (size_t)(i0 + ii) * DD + e0 + kk);
            As[kk + 0][ii] = v.x; As[kk + 1][ii] = v.y;
            As[kk + 2][ii] = v.z; As[kk + 3][ii] = v.w;
            float4 w = *(const float4*)(Aaff + (size_t)(j0 + ii) * DD + e0 + kk);
            Bs[kk + 0][ii] = w.x; Bs[kk + 1][ii] = w.y;
            Bs[kk + 2][ii] = w.z; Bs[kk + 3][ii] = w.w;
        }
        __syncthreads();
#pragma unroll
        for (int kk = 0; kk < 16; kk++) {
            float4 a = *(const float4*)&As[kk][ty * 4];
            float4 b = *(const float4*)&Bs[kk][tx * 4];
            float av[4] = {a.x, a.y, a.z, a.w};
            float bv[4] = {b.x, b.y, b.z, b.w};
#pragma unroll
            for (int r = 0; r < 4; r++)
#pragma unroll
                for (int c = 0; c < 4; c++) acc[r][c] += av[r] * bv[c];
        }
        __syncthreads();
    }

    // --- epilogue: Euler update ---
    float4 bv4 = *(const float4*)(baff + j0 + tx * 4);
    float bv[4] = {bv4.x, bv4.y, bv4.z, bv4.w};
#pragma unroll
    for (int r = 0; r < 4; r++) {
        int i = i0 + ty * 4 + r;
        float4 zv = *(const float4*)(Z + (size_t)i * DD + j0 + tx * 4);
        float zz[4] = {zv.x, zv.y, zv.z, zv.w};
        float4 o;
        float ov[4];
#pragma unroll
        for (int c = 0; c < 4; c++) ov[c] = zz[c] + c_dt * (acc[r][c] + bv[c]);
        o.x = ov[0]; o.y = ov[1]; o.z = ov[2]; o.w = ov[3];
        *(float4*)(Znew + (size_t)i * DD + j0 + tx * 4) = o;
    }
}

// ---------------------------------------------------------------------------
extern "C" void kernel_launch(void* const* d_in, const int* in_sizes, int n_in,
                              void* d_out, int out_size) {
    const float* X    = (const float*)d_in[0];  // [4096, 256]
    const float* A    = (const float*)d_in[1];  // [8, 4096, 256]
    const float* Aaff = (const float*)d_in[2];  // [8, 256, 256]
    const float* baff = (const float*)d_in[3];  // [8, 256]
    float* out = (float*)d_out;                 // [4096, 256]

    void* p;
    cudaGetSymbolAddress(&p, g_Z);
    float* Z0 = (float*)p;
    float* Z1 = Z0 + (size_t)NPTS * DD;
    cudaGetSymbolAddress(&p, g_K);
    float* Kbuf = (float*)p;
    cudaGetSymbolAddress(&p, g_sq);
    float* sqbuf = (float*)p;

    cudaMemcpyAsync(Z0, X, (size_t)NPTS * DD * sizeof(float),
                    cudaMemcpyDeviceToDevice);

    float* cur = Z0;
    float* nxt = Z1;
    for (int t = 0; t < TSTEPS; t++) {
        k_sq<<<NPTS / 8, 256>>>(cur, sqbuf);
        k_gram_exp<<<dim3(NPTS / 64, NPTS / 64), 256>>>(cur, sqbuf, Kbuf);
        float* outp = (t == TSTEPS - 1) ? out : nxt;
        k_step<<<dim3(DD / 64, NPTS / 64), 256>>>(
            cur, Kbuf,
            A + (size_t)t * NPTS * DD,
            Aaff + (size_t)t * DD * DD,
            baff + (size_t)t * DD,
            outp);
        float* tmp = cur; cur = nxt; nxt = tmp;
    }
}

// round 2
// speedup vs baseline: 3.7534x; 3.7534x over previous
#include <cuda_runtime.h>
#include <cuda_bf16.h>
#include <cstdint>
#include <cstring>

#define NPTS 4096
#define DD   256
#define TSTEPS 8

// ---------------- scratch (device globals; no allocs allowed) ----------------
__device__ float         g_Z[2][(size_t)NPTS * DD];       // fp32 ping-pong state
__device__ __nv_bfloat16 g_Kbf[(size_t)NPTS * NPTS];      // 32 MB kernel matrix (bf16)
__device__ __nv_bfloat16 g_Zbf[(size_t)NPTS * DD];        // bf16 copy of current Z
__device__ __nv_bfloat16 g_Abf[(size_t)TSTEPS * NPTS * DD];   // bf16 A
__device__ __nv_bfloat16 g_AaffT[(size_t)TSTEPS * DD * DD];   // bf16 Aaff, transposed [t][e][j]
__device__ float         g_sq[NPTS];

// ---------------- PTX helpers ----------------
#define LDSM4(r, addr)                                                        \
    asm volatile("ldmatrix.sync.aligned.m8n8.x4.shared.b16 {%0,%1,%2,%3}, [%4];" \
                 : "=r"((r)[0]), "=r"((r)[1]), "=r"((r)[2]), "=r"((r)[3])     \
                 : "r"(addr))

#define LDSM4T(r, addr)                                                       \
    asm volatile("ldmatrix.sync.aligned.m8n8.x4.trans.shared.b16 {%0,%1,%2,%3}, [%4];" \
                 : "=r"((r)[0]), "=r"((r)[1]), "=r"((r)[2]), "=r"((r)[3])     \
                 : "r"(addr))

#define MMA16816(d, a, b0, b1)                                                \
    asm volatile("mma.sync.aligned.m16n8k16.row.col.f32.bf16.bf16.f32 "       \
                 "{%0,%1,%2,%3}, {%4,%5,%6,%7}, {%8,%9}, {%0,%1,%2,%3};"      \
                 : "+f"((d)[0]), "+f"((d)[1]), "+f"((d)[2]), "+f"((d)[3])     \
                 : "r"((a)[0]), "r"((a)[1]), "r"((a)[2]), "r"((a)[3]),        \
                   "r"(b0), "r"(b1))

__device__ __forceinline__ uint32_t smem_u32(const void* p) {
    return (uint32_t)__cvta_generic_to_shared(p);
}

__device__ __forceinline__ uint32_t pack_bf16x2(float lo, float hi) {
    __nv_bfloat162 h = __floats2bfloat162_rn(lo, hi);
    uint32_t u;
    memcpy(&u, &h, 4);
    return u;
}

// FFMA-only exp2 (avoids MUFU throughput wall). |rel err| < 1e-6 on [-0.5,0.5] frac.
__device__ __forceinline__ float fexp2(float y) {
    y = fmaxf(y, -120.0f);
    float r = rintf(y);
    float f = y - r;
    float p = 0.0013333558f;
    p = fmaf(p, f, 0.0096181291f);
    p = fmaf(p, f, 0.0555041087f);
    p = fmaf(p, f, 0.2402265069f);
    p = fmaf(p, f, 0.6931471806f);
    p = fmaf(p, f, 1.0f);
    float s = __int_as_float(((int)r + 127) << 23);
    return p * s;
}

// ---------------- one-time input conversion ----------------
__global__ void k_cvtA(const float* __restrict__ A, __nv_bfloat16* __restrict__ Abf, int n4) {
    int i = blockIdx.x * blockDim.x + threadIdx.x;
    if (i >= n4) return;
    float4 v = ((const float4*)A)[i];
    uint2 u;
    u.x = pack_bf16x2(v.x, v.y);
    u.y = pack_bf16x2(v.z, v.w);
    ((uint2*)Abf)[i] = u;
}

__global__ void k_cvtAaffT(const float* __restrict__ Aaff, __nv_bfloat16* __restrict__ AT) {
    int idx = blockIdx.x * blockDim.x + threadIdx.x;
    if (idx >= TSTEPS * DD * DD) return;
    int t = idx / (DD * DD);
    int rem = idx - t * DD * DD;
    int e = rem / DD;
    int j = rem - e * DD;
    AT[idx] = __float2bfloat16(Aaff[(size_t)t * DD * DD + (size_t)j * DD + e]);
}

// ---------------- per-step prep: sq norms + bf16 copy of Z ----------------
__global__ void k_prep(const float* __restrict__ Z, float* __restrict__ sq,
                       __nv_bfloat16* __restrict__ Zbf) {
    int warp = (blockIdx.x * blockDim.x + threadIdx.x) >> 5;
    int lane = threadIdx.x & 31;
    if (warp >= NPTS) return;
    const float4* row = (const float4*)(Z + (size_t)warp * DD);
    float4 v0 = row[lane];
    float4 v1 = row[lane + 32];
    float s = v0.x * v0.x + v0.y * v0.y + v0.z * v0.z + v0.w * v0.w
            + v1.x * v1.x + v1.y * v1.y + v1.z * v1.z + v1.w * v1.w;
    uint2* zb = (uint2*)(Zbf + (size_t)warp * DD);
    uint2 u0, u1;
    u0.x = pack_bf16x2(v0.x, v0.y); u0.y = pack_bf16x2(v0.z, v0.w);
    u1.x = pack_bf16x2(v1.x, v1.y); u1.y = pack_bf16x2(v1.z, v1.w);
    zb[lane] = u0;
    zb[lane + 32] = u1;
#pragma unroll
    for (int o = 16; o > 0; o >>= 1) s += __shfl_xor_sync(0xffffffffu, s, o);
    if (lane == 0) sq[warp] = s;
}

// ---------------- Gram + exp:  K = exp(-(||zi||^2+||zj||^2-2 zi.zj)/512) ----------------
// Block tile 128(i) x 64(j), BK=32. 8 warps as 4(m) x 2(n); warp tile 32x32.
__global__ void k_gram(const __nv_bfloat16* __restrict__ Zbf,
                       const float* __restrict__ sq,
                       __nv_bfloat16* __restrict__ Kout) {
    __shared__ __nv_bfloat16 As[128][40];
    __shared__ __nv_bfloat16 Bs[64][40];

    const int tid = threadIdx.x;
    const int warp = tid >> 5, lane = tid & 31;
    const int wm = warp & 3, wn = warp >> 2;
    const int i0 = blockIdx.y * 128, j0 = blockIdx.x * 64;

    float acc[2][4][4];
#pragma unroll
    for (int a = 0; a < 2; a++)
#pragma unroll
        for (int b = 0; b < 4; b++)
#pragma unroll
            for (int c = 0; c < 4; c++) acc[a][b][c] = 0.0f;

    for (int kc = 0; kc < DD; kc += 32) {
#pragma unroll
        for (int i = 0; i < 2; i++) {
            int idx = tid + i * 256;
            int r = idx >> 2, kg = idx & 3;
            uint4 v = *(const uint4*)(Zbf + (size_t)(i0 + r) * DD + kc + kg * 8);
            *(uint4*)&As[r][kg * 8] = v;
        }
        {
            int r = tid >> 2, kg = tid & 3;
            uint4 v = *(const uint4*)(Zbf + (size_t)(j0 + r) * DD + kc + kg * 8);
            *(uint4*)&Bs[r][kg * 8] = v;
        }
        __syncthreads();
#pragma unroll
        for (int kk = 0; kk < 32; kk += 16) {
            uint32_t a[2][4], b[2][4];
#pragma unroll
            for (int mi = 0; mi < 2; mi++)
                LDSM4(a[mi], smem_u32(&As[wm * 32 + mi * 16 + (lane & 15)][kk + (lane >> 4) * 8]));
#pragma unroll
            for (int g = 0; g < 2; g++)
                LDSM4(b[g], smem_u32(&Bs[wn * 32 + g * 16 + (lane & 15)][kk + (lane >> 4) * 8]));
#pragma unroll
            for (int mi = 0; mi < 2; mi++)
#pragma unroll
                for (int g = 0; g < 2; g++) {
                    MMA16816(acc[mi][2 * g],     a[mi], b[g][0], b[g][2]);
                    MMA16816(acc[mi][2 * g + 1], a[mi], b[g][1], b[g][3]);
                }
        }
        __syncthreads();
    }

    // epilogue: dist -> exp -> bf16 store
    const float Cy = 1.4426950408889634f / 512.0f;  // log2(e) / (2*rho^2)
#pragma unroll
    for (int mi = 0; mi < 2; mi++) {
        int row = i0 + wm * 32 + mi * 16 + (lane >> 2);
        float si0 = sq[row];
        float si1 = sq[row + 8];
#pragma unroll
        for (int ni = 0; ni < 4; ni++) {
            int j = j0 + wn * 32 + ni * 8 + 2 * (lane & 3);
            float2 sj = *(const float2*)(sq + j);
            float k00 = fexp2((2.0f * acc[mi][ni][0] - si0 - sj.x) * Cy);
            float k01 = fexp2((2.0f * acc[mi][ni][1] - si0 - sj.y) * Cy);
            float k10 = fexp2((2.0f * acc[mi][ni][2] - si1 - sj.x) * Cy);
            float k11 = fexp2((2.0f * acc[mi][ni][3] - si1 - sj.y) * Cy);
            *(uint32_t*)(Kout + (size_t)row * NPTS + j)       = pack_bf16x2(k00, k01);
            *(uint32_t*)(Kout + (size_t)(row + 8) * NPTS + j) = pack_bf16x2(k10, k11);
        }
    }
}

// ---------------- step:  Znew = Z + dt*( K@A + Z@Aaff^T + b ) ----------------
// Block tile 128(i) x 64(j over D), BK=32. Phase 0: K(bf16) @ A(bf16) over k=4096.
// Phase 1: Zbf @ AaffT(bf16) over k=256. Same accumulators.
__global__ void k_step(const float* __restrict__ Z,
                       const __nv_bfloat16* __restrict__ Zbf,
                       const __nv_bfloat16* __restrict__ Kbf,
                       const __nv_bfloat16* __restrict__ Abf,    // [4096][256]
                       const __nv_bfloat16* __restrict__ AaffT,  // [256][256]  (e-major)
                       const float* __restrict__ baff,
                       float* __restrict__ Znew) {
    __shared__ __nv_bfloat16 As[128][40];
    __shared__ __nv_bfloat16 Bs[32][72];

    const int tid = threadIdx.x;
    const int warp = tid >> 5, lane = tid & 31;
    const int wm = warp & 3, wn = warp >> 2;
    const int i0 = blockIdx.y * 128, j0 = blockIdx.x * 64;

    float acc[2][4][4];
#pragma unroll
    for (int a = 0; a < 2; a++)
#pragma unroll
        for (int b = 0; b < 4; b++)
#pragma unroll
            for (int c = 0; c < 4; c++) acc[a][b][c] = 0.0f;

#pragma unroll
    for (int phase = 0; phase < 2; phase++) {
        const __nv_bfloat16* Ap = phase ? Zbf : Kbf;
        const size_t lda = phase ? DD : NPTS;
        const __nv_bfloat16* Bp = phase ? AaffT : Abf;  // row-major [k][256]
        const int kmax = phase ? DD : NPTS;

        for (int kc = 0; kc < kmax; kc += 32) {
#pragma unroll
            for (int i = 0; i < 2; i++) {
                int idx = tid + i * 256;
                int r = idx >> 2, kg = idx & 3;
                uint4 v = *(const uint4*)(Ap + (size_t)(i0 + r) * lda + kc + kg * 8);
                *(uint4*)&As[r][kg * 8] = v;
            }
            {
                int k = tid >> 3, ng = tid & 7;
                uint4 v = *(const uint4*)(Bp + (size_t)(kc + k) * DD + j0 + ng * 8);
                *(uint4*)&Bs[k][ng * 8] = v;
            }
            __syncthreads();
#pragma unroll
            for (int kk = 0; kk < 32; kk += 16) {
                uint32_t a[2][4], b[2][4];
#pragma unroll
                for (int mi = 0; mi < 2; mi++)
                    LDSM4(a[mi], smem_u32(&As[wm * 32 + mi * 16 + (lane & 15)][kk + (lane >> 4) * 8]));
#pragma unroll
                for (int g = 0; g < 2; g++)
                    LDSM4T(b[g], smem_u32(&Bs[kk + (lane & 15)][wn * 32 + g * 16 + (lane >> 4) * 8]));
#pragma unroll
                for (int mi = 0; mi < 2; mi++)
#pragma unroll
                    for (int g = 0; g < 2; g++) {
                        MMA16816(acc[mi][2 * g],     a[mi], b[g][0], b[g][1]);
                        MMA16816(acc[mi][2 * g + 1], a[mi], b[g][2], b[g][3]);
                    }
            }
            __syncthreads();
        }
    }

    // epilogue: Euler update (fp32)
    const float dt = 0.125f;
#pragma unroll
    for (int mi = 0; mi < 2; mi++) {
        int row = i0 + wm * 32 + mi * 16 + (lane >> 2);
#pragma unroll
        for (int ni = 0; ni < 4; ni++) {
            int j = j0 + wn * 32 + ni * 8 + 2 * (lane & 3);
            float2 bv = *(const float2*)(baff + j);
            float2 z0 = *(const float2*)(Z + (size_t)row * DD + j);
            float2 z1 = *(const float2*)(Z + (size_t)(row + 8) * DD + j);
            float2 o0, o1;
            o0.x = z0.x + dt * (acc[mi][ni][0] + bv.x);
            o0.y = z0.y + dt * (acc[mi][ni][1] + bv.y);
            o1.x = z1.x + dt * (acc[mi][ni][2] + bv.x);
            o1.y = z1.y + dt * (acc[mi][ni][3] + bv.y);
            *(float2*)(Znew + (size_t)row * DD + j)       = o0;
            *(float2*)(Znew + (size_t)(row + 8) * DD + j) = o1;
        }
    }
}

// ---------------- launch ----------------
extern "C" void kernel_launch(void* const* d_in, const int* in_sizes, int n_in,
                              void* d_out, int out_size) {
    const float* X    = (const float*)d_in[0];  // [4096, 256]
    const float* A    = (const float*)d_in[1];  // [8, 4096, 256]
    const float* Aaff = (const float*)d_in[2];  // [8, 256, 256]
    const float* baff = (const float*)d_in[3];  // [8, 256]
    float* out = (float*)d_out;                 // [4096, 256]

    void* p;
    cudaGetSymbolAddress(&p, g_Z);
    float* Z0 = (float*)p;
    float* Z1 = Z0 + (size_t)NPTS * DD;
    cudaGetSymbolAddress(&p, g_Kbf);   __nv_bfloat16* Kbf   = (__nv_bfloat16*)p;
    cudaGetSymbolAddress(&p, g_Zbf);   __nv_bfloat16* Zbf   = (__nv_bfloat16*)p;
    cudaGetSymbolAddress(&p, g_Abf);   __nv_bfloat16* Abf   = (__nv_bfloat16*)p;
    cudaGetSymbolAddress(&p, g_AaffT); __nv_bfloat16* AaffT = (__nv_bfloat16*)p;
    cudaGetSymbolAddress(&p, g_sq);    float* sqbuf = (float*)p;

    // one-time conversions (per replay; cheap, one pass over inputs)
    {
        int n4 = TSTEPS * NPTS * DD / 4;
        k_cvtA<<<(n4 + 255) / 256, 256>>>(A, Abf, n4);
        int nt = TSTEPS * DD * DD;
        k_cvtAaffT<<<(nt + 255) / 256, 256>>>(Aaff, AaffT);
    }

    cudaMemcpyAsync(Z0, X, (size_t)NPTS * DD * sizeof(float),
                    cudaMemcpyDeviceToDevice);

    float* cur = Z0;
    float* nxt = Z1;
    for (int t = 0; t < TSTEPS; t++) {
        k_prep<<<NPTS / 8, 256>>>(cur, sqbuf, Zbf);
        k_gram<<<dim3(NPTS / 64, NPTS / 128), 256>>>(Zbf, sqbuf, Kbf);
        float* outp = (t == TSTEPS - 1) ? out : nxt;
        k_step<<<dim3(DD / 64, NPTS / 128), 256>>>(
            cur, Zbf, Kbf,
            Abf + (size_t)t * NPTS * DD,
            AaffT + (size_t)t * DD * DD,
            baff + (size_t)t * DD,
            outp);
        float* tmp = cur; cur = nxt; nxt = tmp;
    }
}

// round 3
// speedup vs baseline: 6.6374x; 1.7684x over previous
#include <cuda_runtime.h>
#include <cuda_bf16.h>
#include <cstdint>
#include <cstring>

#define NPTS 4096
#define DD   256
#define TSTEPS 8

// ---------------- scratch (device globals; no allocs allowed) ----------------
__device__ float         g_Z[2][(size_t)NPTS * DD];           // fp32 ping-pong state
__device__ __nv_bfloat16 g_Kbf[(size_t)NPTS * NPTS];          // 32 MB kernel matrix (bf16)
__device__ __nv_bfloat16 g_Zbf[(size_t)NPTS * DD];            // bf16 copy of current Z
__device__ __nv_bfloat16 g_Abf[(size_t)TSTEPS * NPTS * DD];   // bf16 A
__device__ __nv_bfloat16 g_AaffT[(size_t)TSTEPS * DD * DD];   // bf16 Aaff^T [t][e][j]
__device__ float         g_sq[NPTS];
__device__ float         g_P[2][(size_t)NPTS * DD];           // split-K partials (fp32)

// ---------------- PTX helpers ----------------
#define LDSM4(r, addr)                                                        \
    asm volatile("ldmatrix.sync.aligned.m8n8.x4.shared.b16 {%0,%1,%2,%3}, [%4];" \
                 : "=r"((r)[0]), "=r"((r)[1]), "=r"((r)[2]), "=r"((r)[3])     \
                 : "r"(addr))

#define LDSM4T(r, addr)                                                       \
    asm volatile("ldmatrix.sync.aligned.m8n8.x4.trans.shared.b16 {%0,%1,%2,%3}, [%4];" \
                 : "=r"((r)[0]), "=r"((r)[1]), "=r"((r)[2]), "=r"((r)[3])     \
                 : "r"(addr))

#define MMA16816(d, a, b0, b1)                                                \
    asm volatile("mma.sync.aligned.m16n8k16.row.col.f32.bf16.bf16.f32 "       \
                 "{%0,%1,%2,%3}, {%4,%5,%6,%7}, {%8,%9}, {%0,%1,%2,%3};"      \
                 : "+f"((d)[0]), "+f"((d)[1]), "+f"((d)[2]), "+f"((d)[3])     \
                 : "r"((a)[0]), "r"((a)[1]), "r"((a)[2]), "r"((a)[3]),        \
                   "r"(b0), "r"(b1))

#define CP_ASYNC16(dst_u32, src_ptr)                                          \
    asm volatile("cp.async.cg.shared.global [%0], [%1], 16;"                  \
                 :: "r"(dst_u32), "l"(src_ptr) : "memory")

#define CP_COMMIT() asm volatile("cp.async.commit_group;" ::: "memory")
#define CP_WAIT1()  asm volatile("cp.async.wait_group 1;" ::: "memory")
#define CP_WAIT0()  asm volatile("cp.async.wait_group 0;" ::: "memory")

__device__ __forceinline__ uint32_t smem_u32(const void* p) {
    return (uint32_t)__cvta_generic_to_shared(p);
}

__device__ __forceinline__ uint32_t pack_bf16x2(float lo, float hi) {
    __nv_bfloat162 h = __floats2bfloat162_rn(lo, hi);
    uint32_t u;
    memcpy(&u, &h, 4);
    return u;
}

// FFMA-only exp2 (avoids MUFU throughput wall).
__device__ __forceinline__ float fexp2(float y) {
    y = fmaxf(y, -120.0f);
    float r = rintf(y);
    float f = y - r;
    float p = 0.0013333558f;
    p = fmaf(p, f, 0.0096181291f);
    p = fmaf(p, f, 0.0555041087f);
    p = fmaf(p, f, 0.2402265069f);
    p = fmaf(p, f, 0.6931471806f);
    p = fmaf(p, f, 1.0f);
    float s = __int_as_float(((int)r + 127) << 23);
    return p * s;
}

// ---------------- one-time input conversion ----------------
__global__ void k_cvtA(const float* __restrict__ A, __nv_bfloat16* __restrict__ Abf, int n4) {
    int i = blockIdx.x * blockDim.x + threadIdx.x;
    if (i >= n4) return;
    float4 v = ((const float4*)A)[i];
    uint2 u;
    u.x = pack_bf16x2(v.x, v.y);
    u.y = pack_bf16x2(v.z, v.w);
    ((uint2*)Abf)[i] = u;
}

__global__ void k_cvtAaffT(const float* __restrict__ Aaff, __nv_bfloat16* __restrict__ AT) {
    int idx = blockIdx.x * blockDim.x + threadIdx.x;
    if (idx >= TSTEPS * DD * DD) return;
    int t = idx / (DD * DD);
    int rem = idx - t * DD * DD;
    int e = rem / DD;
    int j = rem - e * DD;
    AT[idx] = __float2bfloat16(Aaff[(size_t)t * DD * DD + (size_t)j * DD + e]);
}

// ---------------- per-step prep: sq norms + bf16 copy of Z ----------------
__global__ void k_prep(const float* __restrict__ Z, float* __restrict__ sq,
                       __nv_bfloat16* __restrict__ Zbf) {
    int warp = (blockIdx.x * blockDim.x + threadIdx.x) >> 5;
    int lane = threadIdx.x & 31;
    if (warp >= NPTS) return;
    const float4* row = (const float4*)(Z + (size_t)warp * DD);
    float4 v0 = row[lane];
    float4 v1 = row[lane + 32];
    float s = v0.x * v0.x + v0.y * v0.y + v0.z * v0.z + v0.w * v0.w
            + v1.x * v1.x + v1.y * v1.y + v1.z * v1.z + v1.w * v1.w;
    uint2* zb = (uint2*)(Zbf + (size_t)warp * DD);
    uint2 u0, u1;
    u0.x = pack_bf16x2(v0.x, v0.y); u0.y = pack_bf16x2(v0.z, v0.w);
    u1.x = pack_bf16x2(v1.x, v1.y); u1.y = pack_bf16x2(v1.z, v1.w);
    zb[lane] = u0;
    zb[lane + 32] = u1;
#pragma unroll
    for (int o = 16; o > 0; o >>= 1) s += __shfl_xor_sync(0xffffffffu, s, o);
    if (lane == 0) sq[warp] = s;
}

// ---------------- Gram + exp ----------------
// Block 128x128, BK=32 double-buffered cp.async. 8 warps: 2(m) x 4(n), warp tile 64x32.
__global__ void __launch_bounds__(256, 2)
k_gram(const __nv_bfloat16* __restrict__ Zbf,
       const float* __restrict__ sq,
       __nv_bfloat16* __restrict__ Kout) {
    __shared__ __nv_bfloat16 As[2][128][40];
    __shared__ __nv_bfloat16 Bs[2][128][40];

    const int tid = threadIdx.x;
    const int warp = tid >> 5, lane = tid & 31;
    const int wm = warp & 1, wn = warp >> 1;
    const int i0 = blockIdx.y * 128, j0 = blockIdx.x * 128;

    float acc[4][4][4];
#pragma unroll
    for (int a = 0; a < 4; a++)
#pragma unroll
        for (int b = 0; b < 4; b++)
#pragma unroll
            for (int c = 0; c < 4; c++) acc[a][b][c] = 0.0f;

    const int r_ld = tid >> 2, g_ld = tid & 3;

#define GRAM_LOAD(buf, kc)                                                     \
    do {                                                                       \
        CP_ASYNC16(smem_u32(&As[buf][r_ld][g_ld * 8]),                         \
                   Zbf + (size_t)(i0 + r_ld) * DD + (kc) + g_ld * 8);          \
        CP_ASYNC16(smem_u32(&As[buf][r_ld + 64][g_ld * 8]),                    \
                   Zbf + (size_t)(i0 + r_ld + 64) * DD + (kc) + g_ld * 8);     \
        CP_ASYNC16(smem_u32(&Bs[buf][r_ld][g_ld * 8]),                         \
                   Zbf + (size_t)(j0 + r_ld) * DD + (kc) + g_ld * 8);          \
        CP_ASYNC16(smem_u32(&Bs[buf][r_ld + 64][g_ld * 8]),                    \
                   Zbf + (size_t)(j0 + r_ld + 64) * DD + (kc) + g_ld * 8);     \
    } while (0)

    GRAM_LOAD(0, 0);
    CP_COMMIT();

    for (int it = 0; it < DD / 32; it++) {
        int buf = it & 1;
        if (it + 1 < DD / 32) {
            GRAM_LOAD(buf ^ 1, (it + 1) * 32);
            CP_COMMIT();
            CP_WAIT1();
        } else {
            CP_WAIT0();
        }
        __syncthreads();
#pragma unroll
        for (int kk = 0; kk < 32; kk += 16) {
            uint32_t a[4][4], b[2][4];
#pragma unroll
            for (int mi = 0; mi < 4; mi++)
                LDSM4(a[mi], smem_u32(&As[buf][wm * 64 + mi * 16 + (lane & 15)][kk + (lane >> 4) * 8]));
#pragma unroll
            for (int g = 0; g < 2; g++)
                LDSM4(b[g], smem_u32(&Bs[buf][wn * 32 + g * 16 + (lane & 15)][kk + (lane >> 4) * 8]));
#pragma unroll
            for (int mi = 0; mi < 4; mi++)
#pragma unroll
                for (int g = 0; g < 2; g++) {
                    MMA16816(acc[mi][2 * g],     a[mi], b[g][0], b[g][2]);
                    MMA16816(acc[mi][2 * g + 1], a[mi], b[g][1], b[g][3]);
                }
        }
        __syncthreads();
    }
#undef GRAM_LOAD

    const float Cy = 1.4426950408889634f / 512.0f;
#pragma unroll
    for (int mi = 0; mi < 4; mi++) {
        int row = i0 + wm * 64 + mi * 16 + (lane >> 2);
        float si0 = sq[row];
        float si1 = sq[row + 8];
#pragma unroll
        for (int ni = 0; ni < 4; ni++) {
            int j = j0 + wn * 32 + ni * 8 + 2 * (lane & 3);
            float2 sj = *(const float2*)(sq + j);
            float k00 = fexp2((2.0f * acc[mi][ni][0] - si0 - sj.x) * Cy);
            float k01 = fexp2((2.0f * acc[mi][ni][1] - si0 - sj.y) * Cy);
            float k10 = fexp2((2.0f * acc[mi][ni][2] - si1 - sj.x) * Cy);
            float k11 = fexp2((2.0f * acc[mi][ni][3] - si1 - sj.y) * Cy);
            *(uint32_t*)(Kout + (size_t)row * NPTS + j)       = pack_bf16x2(k00, k01);
            *(uint32_t*)(Kout + (size_t)(row + 8) * NPTS + j) = pack_bf16x2(k10, k11);
        }
    }
}

// ---------------- step GEMM with split-K ----------------
__device__ __forceinline__ void gemm_128x128(
    float (&acc)[4][4][4],
    const __nv_bfloat16* __restrict__ Ap, size_t lda,
    const __nv_bfloat16* __restrict__ Bp,  // row-major [k][DD]
    int kbeg, int kend,
    int i0, int n0, int tid, int lane, int wm, int wn,
    __nv_bfloat16 (*As)[128][40], __nv_bfloat16 (*Bs)[32][136]) {

    const int ra = tid >> 2, ga = tid & 3;
    const int kb = tid >> 4, gb = tid & 15;

#define STEP_LOAD(buf, kc)                                                     \
    do {                                                                       \
        CP_ASYNC16(smem_u32(&As[buf][ra][ga * 8]),                             \
                   Ap + (size_t)(i0 + ra) * lda + (kc) + ga * 8);              \
        CP_ASYNC16(smem_u32(&As[buf][ra + 64][ga * 8]),                        \
                   Ap + (size_t)(i0 + ra + 64) * lda + (kc) + ga * 8);         \
        CP_ASYNC16(smem_u32(&Bs[buf][kb][gb * 8]),                             \
                   Bp + (size_t)((kc) + kb) * DD + n0 + gb * 8);               \
        CP_ASYNC16(smem_u32(&Bs[buf][kb + 16][gb * 8]),                        \
                   Bp + (size_t)((kc) + kb + 16) * DD + n0 + gb * 8);          \
    } while (0)

    const int nIter = (kend - kbeg) / 32;
    STEP_LOAD(0, kbeg);
    CP_COMMIT();

    for (int it = 0; it < nIter; it++) {
        int buf = it & 1;
        if (it + 1 < nIter) {
            STEP_LOAD(buf ^ 1, kbeg + (it + 1) * 32);
            CP_COMMIT();
            CP_WAIT1();
        } else {
            CP_WAIT0();
        }
        __syncthreads();
#pragma unroll
        for (int kk = 0; kk < 32; kk += 16) {
            uint32_t a[4][4], b[2][4];
#pragma unroll
            for (int mi = 0; mi < 4; mi++)
                LDSM4(a[mi], smem_u32(&As[buf][wm * 64 + mi * 16 + (lane & 15)][kk + (lane >> 4) * 8]));
#pragma unroll
            for (int g = 0; g < 2; g++)
                LDSM4T(b[g], smem_u32(&Bs[buf][kk + (lane & 15)][wn * 32 + g * 16 + (lane >> 4) * 8]));
#pragma unroll
            for (int mi = 0; mi < 4; mi++)
#pragma unroll
                for (int g = 0; g < 2; g++) {
                    MMA16816(acc[mi][2 * g],     a[mi], b[g][0], b[g][1]);
                    MMA16816(acc[mi][2 * g + 1], a[mi], b[g][2], b[g][3]);
                }
        }
        __syncthreads();
    }
#undef STEP_LOAD
}

__global__ void __launch_bounds__(256, 2)
k_step(const __nv_bfloat16* __restrict__ Zbf,
       const __nv_bfloat16* __restrict__ Kbf,
       const __nv_bfloat16* __restrict__ Abf,
       const __nv_bfloat16* __restrict__ AaffT,
       float* __restrict__ P0,
       float* __restrict__ P1) {
    __shared__ __nv_bfloat16 As[2][128][40];
    __shared__ __nv_bfloat16 Bs[2][32][136];

    const int tid = threadIdx.x;
    const int warp = tid >> 5, lane = tid & 31;
    const int wm = warp & 1, wn = warp >> 1;
    const int i0 = blockIdx.y * 128, n0 = blockIdx.x * 128;
    const int z = blockIdx.z;
    float* Pout = z ? P1 : P0;

    float acc[4][4][4];
#pragma unroll
    for (int a = 0; a < 4; a++)
#pragma unroll
        for (int b = 0; b < 4; b++)
#pragma unroll
            for (int c = 0; c < 4; c++) acc[a][b][c] = 0.0f;

    gemm_128x128(acc, Kbf, NPTS, Abf, z * (NPTS / 2), (z + 1) * (NPTS / 2),
                 i0, n0, tid, lane, wm, wn, As, Bs);
    if (z == 0)
        gemm_128x128(acc, Zbf, DD, AaffT, 0, DD,
                     i0, n0, tid, lane, wm, wn, As, Bs);

#pragma unroll
    for (int mi = 0; mi < 4; mi++) {
        int row = i0 + wm * 64 + mi * 16 + (lane >> 2);
#pragma unroll
        for (int ni = 0; ni < 4; ni++) {
            int j = n0 + wn * 32 + ni * 8 + 2 * (lane & 3);
            *(float2*)(Pout + (size_t)row * DD + j)       = make_float2(acc[mi][ni][0], acc[mi][ni][1]);
            *(float2*)(Pout + (size_t)(row + 8) * DD + j) = make_float2(acc[mi][ni][2], acc[mi][ni][3]);
        }
    }
}

// ---------------- combine partials + Euler update ----------------
__global__ void k_update(const float* __restrict__ Z,
                         const float* __restrict__ P0,
                         const float* __restrict__ P1,
                         const float* __restrict__ baff,
                         float* __restrict__ Znew) {
    int idx = blockIdx.x * blockDim.x + threadIdx.x;
    int c4 = idx & 63;
    float4 p0 = ((const float4*)P0)[idx];
    float4 p1 = ((const float4*)P1)[idx];
    float4 z  = ((const float4*)Z)[idx];
    float4 bv = ((const float4*)baff)[c4];
    const float dt = 0.125f;
    float4 o;
    o.x = z.x + dt * (p0.x + p1.x + bv.x);
    o.y = z.y + dt * (p0.y + p1.y + bv.y);
    o.z = z.z + dt * (p0.z + p1.z + bv.z);
    o.w = z.w + dt * (p0.w + p1.w + bv.w);
    ((float4*)Znew)[idx] = o;
}

// ---------------- launch ----------------
extern "C" void kernel_launch(void* const* d_in, const int* in_sizes, int n_in,
                              void* d_out, int out_size) {
    const float* X    = (const float*)d_in[0];
    const float* A    = (const float*)d_in[1];
    const float* Aaff = (const float*)d_in[2];
    const float* baff = (const float*)d_in[3];
    float* out = (float*)d_out;

    void* p;
    cudaGetSymbolAddress(&p, g_Z);
    float* Z0 = (float*)p;
    float* Z1 = Z0 + (size_t)NPTS * DD;
    cudaGetSymbolAddress(&p, g_Kbf);   __nv_bfloat16* Kbf   = (__nv_bfloat16*)p;
    cudaGetSymbolAddress(&p, g_Zbf);   __nv_bfloat16* Zbf   = (__nv_bfloat16*)p;
    cudaGetSymbolAddress(&p, g_Abf);   __nv_bfloat16* Abf   = (__nv_bfloat16*)p;
    cudaGetSymbolAddress(&p, g_AaffT); __nv_bfloat16* AaffT = (__nv_bfloat16*)p;
    cudaGetSymbolAddress(&p, g_sq);    float* sqbuf = (float*)p;
    cudaGetSymbolAddress(&p, g_P);
    float* P0 = (float*)p;
    float* P1 = P0 + (size_t)NPTS * DD;

    {
        int n4 = TSTEPS * NPTS * DD / 4;
        k_cvtA<<<(n4 + 255) / 256, 256>>>(A, Abf, n4);
        int nt = TSTEPS * DD * DD;
        k_cvtAaffT<<<(nt + 255) / 256, 256>>>(Aaff, AaffT);
    }

    cudaMemcpyAsync(Z0, X, (size_t)NPTS * DD * sizeof(float),
                    cudaMemcpyDeviceToDevice);

    float* cur = Z0;
    float* nxt = Z1;
    for (int t = 0; t < TSTEPS; t++) {
        k_prep<<<NPTS / 8, 256>>>(cur, sqbuf, Zbf);
        k_gram<<<dim3(NPTS / 128, NPTS / 128), 256>>>(Zbf, sqbuf, Kbf);
        k_step<<<dim3(DD / 128, NPTS / 128, 2), 256>>>(
            Zbf, Kbf,
            Abf + (size_t)t * NPTS * DD,
            AaffT + (size_t)t * DD * DD,
            P0, P1);
        float* outp = (t == TSTEPS - 1) ? out : nxt;
        k_update<<<(NPTS * DD / 4) / 256, 256>>>(cur, P0, P1,
                                                 baff + (size_t)t * DD, outp);
        float* tmp = cur; cur = nxt; nxt = tmp;
    }
}

// round 5
// speedup vs baseline: 7.4683x; 1.1252x over previous
#include <cuda_runtime.h>
#include <cuda_bf16.h>
#include <cstdint>
#include <cstring>

#define NPTS 4096
#define DD   256
#define TSTEPS 8

// ---------------- scratch (device globals; no allocs allowed) ----------------
__device__ float         g_Z[2][(size_t)NPTS * DD];           // fp32 ping-pong state
__device__ __nv_bfloat16 g_Kbf[(size_t)NPTS * NPTS];          // kernel matrix (upper blocks only)
__device__ __nv_bfloat16 g_Zbf[(size_t)NPTS * DD];            // bf16 copy of current Z
__device__ __nv_bfloat16 g_Abf[(size_t)TSTEPS * NPTS * DD];   // bf16 A [t][k][n]
__device__ __nv_bfloat16 g_AaffT[(size_t)TSTEPS * DD * DD];   // bf16 Aaff^T [t][e][j]
__device__ float         g_sq[NPTS];
__device__ float         g_P[2][(size_t)NPTS * DD];           // split-K partials (fp32)

// ---------------- PTX helpers ----------------
#define LDSM4(r, addr)                                                        \
    asm volatile("ldmatrix.sync.aligned.m8n8.x4.shared.b16 {%0,%1,%2,%3}, [%4];" \
                 : "=r"((r)[0]), "=r"((r)[1]), "=r"((r)[2]), "=r"((r)[3])     \
                 : "r"(addr))

#define LDSM4T(r, addr)                                                       \
    asm volatile("ldmatrix.sync.aligned.m8n8.x4.trans.shared.b16 {%0,%1,%2,%3}, [%4];" \
                 : "=r"((r)[0]), "=r"((r)[1]), "=r"((r)[2]), "=r"((r)[3])     \
                 : "r"(addr))

#define MMA16816(d, a, b0, b1)                                                \
    asm volatile("mma.sync.aligned.m16n8k16.row.col.f32.bf16.bf16.f32 "       \
                 "{%0,%1,%2,%3}, {%4,%5,%6,%7}, {%8,%9}, {%0,%1,%2,%3};"      \
                 : "+f"((d)[0]), "+f"((d)[1]), "+f"((d)[2]), "+f"((d)[3])     \
                 : "r"((a)[0]), "r"((a)[1]), "r"((a)[2]), "r"((a)[3]),        \
                   "r"(b0), "r"(b1))

#define CP_ASYNC16(dst_u32, src_ptr)                                          \
    asm volatile("cp.async.cg.shared.global [%0], [%1], 16;"                  \
                 :: "r"(dst_u32), "l"(src_ptr) : "memory")

#define CP_COMMIT() asm volatile("cp.async.commit_group;" ::: "memory")
#define CP_WAIT1()  asm volatile("cp.async.wait_group 1;" ::: "memory")
#define CP_WAIT0()  asm volatile("cp.async.wait_group 0;" ::: "memory")

__device__ __forceinline__ uint32_t smem_u32(const void* p) {
    return (uint32_t)__cvta_generic_to_shared(p);
}

__device__ __forceinline__ uint32_t pack_bf16x2(float lo, float hi) {
    __nv_bfloat162 h = __floats2bfloat162_rn(lo, hi);
    uint32_t u;
    memcpy(&u, &h, 4);
    return u;
}

// FFMA-only exp2 (avoids MUFU throughput wall).
__device__ __forceinline__ float fexp2(float y) {
    y = fmaxf(y, -120.0f);
    float r = rintf(y);
    float f = y - r;
    float p = 0.0013333558f;
    p = fmaf(p, f, 0.0096181291f);
    p = fmaf(p, f, 0.0555041087f);
    p = fmaf(p, f, 0.2402265069f);
    p = fmaf(p, f, 0.6931471806f);
    p = fmaf(p, f, 1.0f);
    float s = __int_as_float(((int)r + 127) << 23);
    return p * s;
}

// ---------------- one-time input conversion ----------------
__global__ void k_cvtA(const float* __restrict__ A, __nv_bfloat16* __restrict__ Abf, int n4) {
    int i = blockIdx.x * blockDim.x + threadIdx.x;
    if (i >= n4) return;
    float4 v = ((const float4*)A)[i];
    uint2 u;
    u.x = pack_bf16x2(v.x, v.y);
    u.y = pack_bf16x2(v.z, v.w);
    ((uint2*)Abf)[i] = u;
}

__global__ void k_cvtAaffT(const float* __restrict__ Aaff, __nv_bfloat16* __restrict__ AT) {
    int idx = blockIdx.x * blockDim.x + threadIdx.x;
    if (idx >= TSTEPS * DD * DD) return;
    int t = idx / (DD * DD);
    int rem = idx - t * DD * DD;
    int e = rem / DD;
    int j = rem - e * DD;
    AT[idx] = __float2bfloat16(Aaff[(size_t)t * DD * DD + (size_t)j * DD + e]);
}

// ---------------- per-step prep: sq norms + bf16 copy of Z ----------------
__global__ void k_prep(const float* __restrict__ Z, float* __restrict__ sq,
                       __nv_bfloat16* __restrict__ Zbf) {
    int warp = (blockIdx.x * blockDim.x + threadIdx.x) >> 5;
    int lane = threadIdx.x & 31;
    if (warp >= NPTS) return;
    const float4* row = (const float4*)(Z + (size_t)warp * DD);
    float4 v0 = row[lane];
    float4 v1 = row[lane + 32];
    float s = v0.x * v0.x + v0.y * v0.y + v0.z * v0.z + v0.w * v0.w
            + v1.x * v1.x + v1.y * v1.y + v1.z * v1.z + v1.w * v1.w;
    uint2* zb = (uint2*)(Zbf + (size_t)warp * DD);
    uint2 u0, u1;
    u0.x = pack_bf16x2(v0.x, v0.y); u0.y = pack_bf16x2(v0.z, v0.w);
    u1.x = pack_bf16x2(v1.x, v1.y); u1.y = pack_bf16x2(v1.z, v1.w);
    zb[lane] = u0;
    zb[lane + 32] = u1;
#pragma unroll
    for (int o = 16; o > 0; o >>= 1) s += __shfl_xor_sync(0xffffffffu, s, o);
    if (lane == 0) sq[warp] = s;
}

// ---------------- Gram + exp (upper-triangle blocks only) ----------------
// Block 128x128, BK=32 double-buffered cp.async. 8 warps: 2(m) x 4(n), warp tile 64x32.
__global__ void __launch_bounds__(256, 2)
k_gram(const __nv_bfloat16* __restrict__ Zbf,
       const float* __restrict__ sq,
       __nv_bfloat16* __restrict__ Kout) {
    // symmetry: only compute blocks with col-block >= row-block
    if (blockIdx.x < blockIdx.y) return;

    __shared__ __nv_bfloat16 As[2][128][40];
    __shared__ __nv_bfloat16 Bs[2][128][40];

    const int tid = threadIdx.x;
    const int warp = tid >> 5, lane = tid & 31;
    const int wm = warp & 1, wn = warp >> 1;
    const int i0 = blockIdx.y * 128, j0 = blockIdx.x * 128;

    float acc[4][4][4];
#pragma unroll
    for (int a = 0; a < 4; a++)
#pragma unroll
        for (int b = 0; b < 4; b++)
#pragma unroll
            for (int c = 0; c < 4; c++) acc[a][b][c] = 0.0f;

    const int r_ld = tid >> 2, g_ld = tid & 3;

#define GRAM_LOAD(buf, kc)                                                     \
    do {                                                                       \
        CP_ASYNC16(smem_u32(&As[buf][r_ld][g_ld * 8]),                         \
                   Zbf + (size_t)(i0 + r_ld) * DD + (kc) + g_ld * 8);          \
        CP_ASYNC16(smem_u32(&As[buf][r_ld + 64][g_ld * 8]),                    \
                   Zbf + (size_t)(i0 + r_ld + 64) * DD + (kc) + g_ld * 8);     \
        CP_ASYNC16(smem_u32(&Bs[buf][r_ld][g_ld * 8]),                         \
                   Zbf + (size_t)(j0 + r_ld) * DD + (kc) + g_ld * 8);          \
        CP_ASYNC16(smem_u32(&Bs[buf][r_ld + 64][g_ld * 8]),                    \
                   Zbf + (size_t)(j0 + r_ld + 64) * DD + (kc) + g_ld * 8);     \
    } while (0)

    GRAM_LOAD(0, 0);
    CP_COMMIT();

    for (int it = 0; it < DD / 32; it++) {
        int buf = it & 1;
        if (it + 1 < DD / 32) {
            GRAM_LOAD(buf ^ 1, (it + 1) * 32);
            CP_COMMIT();
            CP_WAIT1();
        } else {
            CP_WAIT0();
        }
        __syncthreads();
#pragma unroll
        for (int kk = 0; kk < 32; kk += 16) {
            uint32_t a[4][4], b[2][4];
#pragma unroll
            for (int mi = 0; mi < 4; mi++)
                LDSM4(a[mi], smem_u32(&As[buf][wm * 64 + mi * 16 + (lane & 15)][kk + (lane >> 4) * 8]));
#pragma unroll
            for (int g = 0; g < 2; g++)
                LDSM4(b[g], smem_u32(&Bs[buf][wn * 32 + g * 16 + (lane & 15)][kk + (lane >> 4) * 8]));
#pragma unroll
            for (int mi = 0; mi < 4; mi++)
#pragma unroll
                for (int g = 0; g < 2; g++) {
                    MMA16816(acc[mi][2 * g],     a[mi], b[g][0], b[g][2]);
                    MMA16816(acc[mi][2 * g + 1], a[mi], b[g][1], b[g][3]);
                }
        }
        __syncthreads();
    }
#undef GRAM_LOAD

    const float Cy = 1.4426950408889634f / 512.0f;
#pragma unroll
    for (int mi = 0; mi < 4; mi++) {
        int row = i0 + wm * 64 + mi * 16 + (lane >> 2);
        float si0 = sq[row];
        float si1 = sq[row + 8];
#pragma unroll
        for (int ni = 0; ni < 4; ni++) {
            int j = j0 + wn * 32 + ni * 8 + 2 * (lane & 3);
            float2 sj = *(const float2*)(sq + j);
            float k00 = fexp2((2.0f * acc[mi][ni][0] - si0 - sj.x) * Cy);
            float k01 = fexp2((2.0f * acc[mi][ni][1] - si0 - sj.y) * Cy);
            float k10 = fexp2((2.0f * acc[mi][ni][2] - si1 - sj.x) * Cy);
            float k11 = fexp2((2.0f * acc[mi][ni][3] - si1 - sj.y) * Cy);
            *(uint32_t*)(Kout + (size_t)row * NPTS + j)       = pack_bf16x2(k00, k01);
            *(uint32_t*)(Kout + (size_t)(row + 8) * NPTS + j) = pack_bf16x2(k10, k11);
        }
    }
}

// ---------------- step GEMM with split-K + symmetric K reads ----------------
// A-operand tile (K matrix rows) comes either from the stored upper block
// (normal, [128 m][32 k] layout) or, for kc < i0, from the mirrored stored
// block K[kc..][i0..] loaded k-major ([32 k][128 m]) and consumed via
// ldmatrix.trans with fragments reordered {t0,t2,t1,t3}.
__device__ __forceinline__ void gemm_128x128_sym(
    float (&acc)[4][4][4],
    const __nv_bfloat16* __restrict__ Kbf,   // symmetric matrix (upper blocks valid)
    const __nv_bfloat16* __restrict__ Bp,    // row-major [k][DD]
    int kbeg, int kend,
    int i0, int n0, int tid, int lane, int wm, int wn,
    __nv_bfloat16* AsBuf,                    // 2 stages x 5120 bf16
    __nv_bfloat16 (*Bs)[32][136],
    bool sym)                                // true: K-matrix source (use mirror rule)
{
    const int ra = tid >> 2, ga = tid & 3;    // normal A fill
    const int km = tid >> 4, gm = tid & 15;   // mirror A fill (32 k-rows x 16 chunks)
    const int kb = tid >> 4, gb = tid & 15;   // B fill

    const size_t lda = sym ? (size_t)NPTS : (size_t)DD;

#define SYM_LOAD(buf, kc)                                                      \
    do {                                                                       \
        __nv_bfloat16* Adst = AsBuf + (buf) * 5120;                            \
        bool mirror = sym && ((kc) < i0);                                      \
        if (!mirror) {                                                         \
            CP_ASYNC16(smem_u32(Adst + ra * 40 + ga * 8),                      \
                       Kbf + (size_t)(i0 + ra) * lda + (kc) + ga * 8);         \
            CP_ASYNC16(smem_u32(Adst + (ra + 64) * 40 + ga * 8),               \
                       Kbf + (size_t)(i0 + ra + 64) * lda + (kc) + ga * 8);    \
        } else {                                                               \
            CP_ASYNC16(smem_u32(Adst + km * 136 + gm * 8),                     \
                       Kbf + (size_t)((kc) + km) * NPTS + i0 + gm * 8);        \
            CP_ASYNC16(smem_u32(Adst + (km + 16) * 136 + gm * 8),              \
                       Kbf + (size_t)((kc) + km + 16) * NPTS + i0 + gm * 8);   \
        }                                                                      \
        CP_ASYNC16(smem_u32(&Bs[buf][kb][gb * 8]),                             \
                   Bp + (size_t)((kc) + kb) * DD + n0 + gb * 8);               \
        CP_ASYNC16(smem_u32(&Bs[buf][kb + 16][gb * 8]),                        \
                   Bp + (size_t)((kc) + kb + 16) * DD + n0 + gb * 8);          \
    } while (0)

    const int nIter = (kend - kbeg) / 32;
    SYM_LOAD(0, kbeg);
    CP_COMMIT();

    for (int it = 0; it < nIter; it++) {
        int buf = it & 1;
        int kc = kbeg + it * 32;
        bool mirror = sym && (kc < i0);
        if (it + 1 < nIter) {
            SYM_LOAD(buf ^ 1, kc + 32);
            CP_COMMIT();
            CP_WAIT1();
        } else {
            CP_WAIT0();
        }
        __syncthreads();
        const __nv_bfloat16* Asrc = AsBuf + buf * 5120;
#pragma unroll
        for (int kk = 0; kk < 32; kk += 16) {
            uint32_t a[4][4], b[2][4];
            if (!mirror) {
#pragma unroll
                for (int mi = 0; mi < 4; mi++)
                    LDSM4(a[mi], smem_u32(Asrc + (wm * 64 + mi * 16 + (lane & 15)) * 40
                                               + kk + (lane >> 4) * 8));
            } else {
#pragma unroll
                for (int mi = 0; mi < 4; mi++) {
                    uint32_t t[4];
                    LDSM4T(t, smem_u32(Asrc + (kk + (lane & 15)) * 136
                                            + wm * 64 + mi * 16 + (lane >> 4) * 8));
                    a[mi][0] = t[0]; a[mi][1] = t[2]; a[mi][2] = t[1]; a[mi][3] = t[3];
                }
            }
#pragma unroll
            for (int g = 0; g < 2; g++)
                LDSM4T(b[g], smem_u32(&Bs[buf][kk + (lane & 15)][wn * 32 + g * 16 + (lane >> 4) * 8]));
#pragma unroll
            for (int mi = 0; mi < 4; mi++)
#pragma unroll
                for (int g = 0; g < 2; g++) {
                    MMA16816(acc[mi][2 * g],     a[mi], b[g][0], b[g][1]);
                    MMA16816(acc[mi][2 * g + 1], a[mi], b[g][2], b[g][3]);
                }
        }
        __syncthreads();
    }
#undef SYM_LOAD
}

__global__ void __launch_bounds__(256, 2)
k_step(const __nv_bfloat16* __restrict__ Zbf,
       const __nv_bfloat16* __restrict__ Kbf,
       const __nv_bfloat16* __restrict__ Abf,
       const __nv_bfloat16* __restrict__ AaffT,
       float* __restrict__ P0,
       float* __restrict__ P1) {
    __shared__ __nv_bfloat16 AsBuf[2 * 5120];
    __shared__ __nv_bfloat16 Bs[2][32][136];

    const int tid = threadIdx.x;
    const int warp = tid >> 5, lane = tid & 31;
    const int wm = warp & 1, wn = warp >> 1;
    const int i0 = blockIdx.y * 128, n0 = blockIdx.x * 128;
    const int z = blockIdx.z;
    float* Pout = z ? P1 : P0;

    float acc[4][4][4];
#pragma unroll
    for (int a = 0; a < 4; a++)
#pragma unroll
        for (int b = 0; b < 4; b++)
#pragma unroll
            for (int c = 0; c < 4; c++) acc[a][b][c] = 0.0f;

    gemm_128x128_sym(acc, Kbf, Abf, z * (NPTS / 2), (z + 1) * (NPTS / 2),
                     i0, n0, tid, lane, wm, wn, AsBuf, Bs, /*sym=*/true);
    if (z == 0)
        gemm_128x128_sym(acc, Zbf, AaffT, 0, DD,
                         i0, n0, tid, lane, wm, wn, AsBuf, Bs, /*sym=*/false);

#pragma unroll
    for (int mi = 0; mi < 4; mi++) {
        int row = i0 + wm * 64 + mi * 16 + (lane >> 2);
#pragma unroll
        for (int ni = 0; ni < 4; ni++) {
            int j = n0 + wn * 32 + ni * 8 + 2 * (lane & 3);
            *(float2*)(Pout + (size_t)row * DD + j)       = make_float2(acc[mi][ni][0], acc[mi][ni][1]);
            *(float2*)(Pout + (size_t)(row + 8) * DD + j) = make_float2(acc[mi][ni][2], acc[mi][ni][3]);
        }
    }
}

// ---------------- combine partials + Euler update ----------------
__global__ void k_update(const float* __restrict__ Z,
                         const float* __restrict__ P0,
                         const float* __restrict__ P1,
                         const float* __restrict__ baff,
                         float* __restrict__ Znew) {
    int idx = blockIdx.x * blockDim.x + threadIdx.x;
    int c4 = idx & 63;
    float4 p0 = ((const float4*)P0)[idx];
    float4 p1 = ((const float4*)P1)[idx];
    float4 z  = ((const float4*)Z)[idx];
    float4 bv = ((const float4*)baff)[c4];
    const float dt = 0.125f;
    float4 o;
    o.x = z.x + dt * (p0.x + p1.x + bv.x);
    o.y = z.y + dt * (p0.y + p1.y + bv.y);
    o.z = z.z + dt * (p0.z + p1.z + bv.z);
    o.w = z.w + dt * (p0.w + p1.w + bv.w);
    ((float4*)Znew)[idx] = o;
}

// ---------------- launch ----------------
extern "C" void kernel_launch(void* const* d_in, const int* in_sizes, int n_in,
                              void* d_out, int out_size) {
    const float* X    = (const float*)d_in[0];
    const float* A    = (const float*)d_in[1];
    const float* Aaff = (const float*)d_in[2];
    const float* baff = (const float*)d_in[3];
    float* out = (float*)d_out;

    void* p;
    cudaGetSymbolAddress(&p, g_Z);
    float* Z0 = (float*)p;
    float* Z1 = Z0 + (size_t)NPTS * DD;
    cudaGetSymbolAddress(&p, g_Kbf);   __nv_bfloat16* Kbf   = (__nv_bfloat16*)p;
    cudaGetSymbolAddress(&p, g_Zbf);   __nv_bfloat16* Zbf   = (__nv_bfloat16*)p;
    cudaGetSymbolAddress(&p, g_Abf);   __nv_bfloat16* Abf   = (__nv_bfloat16*)p;
    cudaGetSymbolAddress(&p, g_AaffT); __nv_bfloat16* AaffT = (__nv_bfloat16*)p;
    cudaGetSymbolAddress(&p, g_sq);    float* sqbuf = (float*)p;
    cudaGetSymbolAddress(&p, g_P);
    float* P0 = (float*)p;
    float* P1 = P0 + (size_t)NPTS * DD;

    {
        int n4 = TSTEPS * NPTS * DD / 4;
        k_cvtA<<<(n4 + 255) / 256, 256>>>(A, Abf, n4);
        int nt = TSTEPS * DD * DD;
        k_cvtAaffT<<<(nt + 255) / 256, 256>>>(Aaff, AaffT);
    }

    cudaMemcpyAsync(Z0, X, (size_t)NPTS * DD * sizeof(float),
                    cudaMemcpyDeviceToDevice);

    float* cur = Z0;
    float* nxt = Z1;
    for (int t = 0; t < TSTEPS; t++) {
        k_prep<<<NPTS / 8, 256>>>(cur, sqbuf, Zbf);
        k_gram<<<dim3(NPTS / 128, NPTS / 128), 256>>>(Zbf, sqbuf, Kbf);
        k_step<<<dim3(DD / 128, NPTS / 128, 2), 256>>>(
            Zbf, Kbf,
            Abf + (size_t)t * NPTS * DD,
            AaffT + (size_t)t * DD * DD,
            P0, P1);
        float* outp = (t == TSTEPS - 1) ? out : nxt;
        k_update<<<(NPTS * DD / 4) / 256, 256>>>(cur, P0, P1,
                                                 baff + (size_t)t * DD, outp);
        float* tmp = cur; cur = nxt; nxt = tmp;
    }
}